// round 15
// baseline (speedup 1.0000x reference)
#include <cuda_runtime.h>
#include <cuda_bf16.h>
#include <cstdint>

// Problem constants
constexpr int kB   = 64;     // batch
constexpr int kC   = 128;    // CSIZE
constexpr int kV   = 256;    // VIEW
constexpr int kN   = 2000;   // N_WRD
constexpr int kE   = 32;     // EMB
constexpr int TR   = 64;     // n-rows per block

// shared memory layout (float indices), TR=64 / 256-thread / 2 CTA-per-SM
constexpr int OFF_H   = 0;                      // 16384: relation/route fp32 64x256
                                                //   overlays: P3 B chunk (256x36 u32), fceT (32x132 u32)
constexpr int OFF_HA  = 16384;                  // 8256: h1/h2 bf16 64x129 u32
                                                //   overlays: vsT (256x17), P5 tiles (7680)
constexpr int OFF_EMB = OFF_HA + 8256;          // 1088: emb bf16 64x17 u32
constexpr int OFF_WC  = OFF_EMB + 1088;         // 192
constexpr int OFF_ACT = OFF_WC + 192;           // 64
constexpr int SM_FLOATS = OFF_ACT + 64;         // 25984
constexpr int SM_BYTES  = SM_FLOATS * 4;        // 103936 B  (2 CTAs/SM)

constexpr int HA_U32_STRIDE  = 129;  // 258 bf16 per row
constexpr int BT_U32_STRIDE  = 36;   // P3 B chunk rows (64 bf16 = 32 u32 + 4 pad)
constexpr int FCE_U32_STRIDE = 132;  // fceT rows (256 bf16 + pad)
constexpr int VST_U32_STRIDE = 17;   // vsT rows (32 bf16 + pad)
constexpr int EMB_U32_STRIDE = 17;   // emb rows (32 bf16 + pad)
constexpr int P5_STRIDE      = 20;   // P5 tiles (32 bf16 = 16 u32 + 4 pad)

__device__ float g_h0[kB * 512];
__device__ float g_wcode[kB * 6000];
__device__ __align__(16) __nv_bfloat16 g_fc2bt[256 * 256];  // fc2 Bt[n][k]
__device__ __align__(16) __nv_bfloat16 g_fceT[32 * 256];    // fce Bt[n][k]
__device__ __align__(16) __nv_bfloat16 g_vsTbf[256 * 32];   // vs [v][e]
__device__ __align__(16) __nv_bfloat16 g_vchi[kB * kC * kV]; // view_cell hi
__device__ __align__(16) __nv_bfloat16 g_vclo[kB * kC * kV]; // view_cell lo

// ---------------- helpers ---------------------------------------------------
__device__ __forceinline__ uint32_t pack_bf16(float lo, float hi) {
    uint32_t r;
    asm("cvt.rn.bf16x2.f32 %0, %1, %2;" : "=r"(r) : "f"(hi), "f"(lo));
    return r;
}
__device__ __forceinline__ float bf16lo(uint32_t u) { return __uint_as_float(u << 16); }
__device__ __forceinline__ float bf16hi(uint32_t u) { return __uint_as_float(u & 0xffff0000u); }
__device__ __forceinline__ void mma_bf16(float& d0, float& d1, float& d2, float& d3,
                                         uint32_t a0, uint32_t a1, uint32_t a2, uint32_t a3,
                                         uint32_t b0, uint32_t b1) {
    asm volatile(
        "mma.sync.aligned.m16n8k16.row.col.f32.bf16.bf16.f32 "
        "{%0,%1,%2,%3}, {%4,%5,%6,%7}, {%8,%9}, {%0,%1,%2,%3};"
        : "+f"(d0), "+f"(d1), "+f"(d2), "+f"(d3)
        : "r"(a0), "r"(a1), "r"(a2), "r"(a3), "r"(b0), "r"(b1));
}

// ---------------------------------------------------------------------------
// Prep kernel (merged): all independent setup work in ONE launch.
//   blocks [0,64):      h0 per batch
//   blocks [64,72):     vsTbf
//   blocks [72,84):     g_wcode bias init
//   blocks [84,340):    fc2 transpose+bf16 cvt
//   blocks [340,372):   fce transpose+bf16 cvt
//   blocks [372,2420):  view_cell hi/lo split
// ---------------------------------------------------------------------------
__global__ __launch_bounds__(512)
void prep_kernel(const float* __restrict__ v,
                 const float* __restrict__ w2c_w1,
                 const float* __restrict__ w2c_b1,
                 const float* __restrict__ w2c_b2,
                 const float* __restrict__ vse_w1,
                 const float* __restrict__ vse_b1,
                 const float* __restrict__ vse_w2,
                 const float* __restrict__ vse_b2,
                 const float* __restrict__ fc2_w,
                 const float* __restrict__ fce_w,
                 const float* __restrict__ view_cell) {
    int blk = blockIdx.x;
    int t = threadIdx.x;  // 512
    if (blk < 64) {
        float acc = w2c_b1[t];
#pragma unroll
        for (int i = 0; i < 7; i++) acc += v[blk * 7 + i] * w2c_w1[i * 512 + t];
        g_h0[blk * 512 + t] = fmaxf(acc, 0.f);
    } else if (blk < 72) {
        int vb = (blk - 64) * 32;
        __shared__ float hid[32][128];
        for (int idx = t; idx < 32 * 128; idx += 512) {
            int vv = idx >> 7, h = idx & 127;
            int vg = vb + vv;
            int xi = vg >> 4, yi = vg & 15;
            float x = -1.f + (2.f / 15.f) * (float)xi;
            float y = -1.f + (2.f / 15.f) * (float)yi;
            float a = x * vse_w1[h] + y * vse_w1[128 + h] + vse_b1[h];
            hid[vv][h] = fmaxf(a, 0.f);
        }
        __syncthreads();
        for (int idx = t; idx < 32 * 32; idx += 512) {
            int e = idx >> 5, vv = idx & 31;
            float acc = vse_b2[e];
#pragma unroll 8
            for (int h = 0; h < 128; h++) acc += hid[vv][h] * vse_w2[h * kE + e];
            g_vsTbf[(vb + vv) * 32 + e] = __float2bfloat16(acc);
        }
    } else if (blk < 84) {
        for (int i = (blk - 72) * 512 + t; i < kB * 6000; i += 12 * 512) {
            int col = i % 6000;
            g_wcode[i] = w2c_b2[col];
        }
    } else if (blk < 340) {
        int p = (blk - 84) * 256 + (t & 255);   // 65536 elems over 256 blocks
        if (t < 256) {
            int k = p >> 8, n = p & 255;
            g_fc2bt[n * 256 + k] = __float2bfloat16(fc2_w[p]);
        }
    } else if (blk < 372) {
        int p = (blk - 340) * 256 + (t & 255);  // 8192 elems over 32 blocks
        if (t < 256) {
            int k = p >> 5, n = p & 31;
            g_fceT[n * 256 + k] = __float2bfloat16(fce_w[p]);
        }
    } else {
        int p = (blk - 372) * 512 + t;   // pair index, 1048576 pairs
        float2 f = ((const float2*)view_cell)[p];
        uint32_t h = pack_bf16(f.x, f.y);
        ((uint32_t*)g_vchi)[p] = h;
        ((uint32_t*)g_vclo)[p] = pack_bf16(f.x - bf16lo(h), f.y - bf16hi(h));
    }
}

// ---------------------------------------------------------------------------
// wcode: k-split GEMM with atomic accumulation (bias pre-written by prep).
// ---------------------------------------------------------------------------
__global__ __launch_bounds__(128)
void wcode_kernel(const float* __restrict__ w2c_w2) {
    __shared__ float h0s[64 * 65];  // [kk][b]
    int t = threadIdx.x;
    int col = blockIdx.x * 128 + t;
    int k0 = blockIdx.y * 64;
    bool ok = col < 6000;

    for (int idx = t; idx < 64 * 64; idx += 128) {
        int b = idx >> 6, kk = idx & 63;
        h0s[kk * 65 + b] = g_h0[b * 512 + k0 + kk];
    }
    __syncthreads();

    float acc[64];
#pragma unroll
    for (int b = 0; b < 64; b++) acc[b] = 0.f;
#pragma unroll 4
    for (int kk = 0; kk < 64; kk++) {
        float w = ok ? w2c_w2[(k0 + kk) * 6000 + col] : 0.f;
        const float* hrow = h0s + kk * 65;
#pragma unroll
        for (int b = 0; b < 64; b++) acc[b] = fmaf(hrow[b], w, acc[b]);
    }
    if (ok) {
#pragma unroll
        for (int b = 0; b < 64; b++) atomicAdd(&g_wcode[b * 6000 + col], acc[b]);
    }
}

// ---------------------------------------------------------------------------
// Mega kernel: one block = (batch b, 64 word rows). 256 threads, 2 CTAs/SM.
// P3/P4a/P4b bf16 HMMA; P5 split-bf16 HMMA (3-product emulation).
// ---------------------------------------------------------------------------
__global__ __launch_bounds__(256, 2)
void mega_kernel(const float* __restrict__ fc1_w,  const float* __restrict__ fc1_b,
                 const float* __restrict__ fc2_b,
                 const float* __restrict__ fca_w,  const float* __restrict__ fca_b,
                 const float* __restrict__ fce_b,
                 float* __restrict__ out) {
    extern __shared__ float sm[];
    float*    H    = sm + OFF_H;                 // relation -> route, stride 256
    uint32_t* Hu   = (uint32_t*)H;               // overlays: BT / fceT
    uint32_t* habu = (uint32_t*)(sm + OFF_HA);   // h1/h2 bf16, u32 stride 129
    uint32_t* embu = (uint32_t*)(sm + OFF_EMB);  // emb bf16, u32 stride 17
    float*    WC   = sm + OFF_WC;
    float*    ACT  = sm + OFF_ACT;
    // HA overlays
    uint32_t* VST = habu;                        // vsT 256x17 (P4b)
    uint32_t* AH  = habu;                        // P5: 128x20
    uint32_t* AL  = AH + 128 * P5_STRIDE;        //     128x20
    uint32_t* BH  = AL + 128 * P5_STRIDE;        //     64x20
    uint32_t* BL  = BH + 64 * P5_STRIDE;         //     64x20 (total 7680 <= 8256)

    const int t    = threadIdx.x;
    const int lane = t & 31;
    const int wid  = t >> 5;          // 8 warps
    const int b    = blockIdx.y;
    const int n0   = blockIdx.x * TR;
    const int rbase = wid * 8;
    const int qrow = lane >> 2;       // 0..7
    const int qk   = lane & 3;        // 0..3

    // ---- P1: fetch wcode tile ----------------------------------------------
    if (t < 192) {
        int c = n0 * 3 + t;
        WC[t] = (c < 6000) ? g_wcode[b * 6000 + c] : 0.f;
    }
    __syncthreads();

    // ---- P2: h1 = relu(wcode @ fc1_w + b1) -> HA (bf16 pairs) --------------
    for (int p = t; p < 64 * 128; p += 256) {
        int row = p >> 7, j = p & 127;
        float wc0 = WC[row * 3 + 0], wc1 = WC[row * 3 + 1], wc2 = WC[row * 3 + 2];
        int c0 = 2 * j;
        float f0 = fmaxf(fc1_b[c0]     + wc0 * fc1_w[c0]     + wc1 * fc1_w[256 + c0]     + wc2 * fc1_w[512 + c0],     0.f);
        float f1 = fmaxf(fc1_b[c0 + 1] + wc0 * fc1_w[c0 + 1] + wc1 * fc1_w[256 + c0 + 1] + wc2 * fc1_w[512 + c0 + 1], 0.f);
        habu[row * HA_U32_STRIDE + j] = pack_bf16(f0, f1);
    }
    __syncthreads();

    // ---- P3: h2 = relu(h1 @ fc2_w + b2) via bf16 HMMA (M=64,N=256,K=256) ---
    // warp (rg = wid>>1, ng = wid&1): rows rg*16..+15, cols ng*128..+127
    const int rg = wid >> 1, ng = wid & 1;
    const int m0 = rg * 16;
    const int n0w = ng * 128;

    float d[16][4];
#pragma unroll
    for (int nt = 0; nt < 16; nt++)
#pragma unroll
        for (int i = 0; i < 4; i++) d[nt][i] = 0.f;

    for (int kc = 0; kc < 4; kc++) {           // k-chunks of 64
        __syncthreads();
        {   // copy B chunk: g_fc2bt[n][kc*64..+64] -> Hu[n][36 u32], row per thread
            const uint4* src = (const uint4*)((const uint32_t*)g_fc2bt + t * 128 + kc * 32);
            uint4* dst = (uint4*)(Hu + t * BT_U32_STRIDE);
#pragma unroll
            for (int j = 0; j < 8; j++) dst[j] = src[j];
        }
        __syncthreads();
#pragma unroll
        for (int ks = 0; ks < 4; ks++) {
            int kg = kc * 64 + ks * 16;
            int aidx = (m0 + qrow) * HA_U32_STRIDE + (kg >> 1) + qk;
            uint32_t a0 = habu[aidx];
            uint32_t a1 = habu[aidx + 8 * HA_U32_STRIDE];
            uint32_t a2 = habu[aidx + 4];
            uint32_t a3 = habu[aidx + 8 * HA_U32_STRIDE + 4];
#pragma unroll
            for (int nt = 0; nt < 16; nt++) {
                int c = n0w + nt * 8 + qrow;
                int bidx = c * BT_U32_STRIDE + ks * 8 + qk;
                mma_bf16(d[nt][0], d[nt][1], d[nt][2], d[nt][3],
                         a0, a1, a2, a3, Hu[bidx], Hu[bidx + 4]);
            }
        }
    }
    __syncthreads();
    // writeback h2 = relu(d + fc2_b) as bf16 into HA (h1 dead)
    {
        int rlo = m0 + qrow;
#pragma unroll
        for (int nt = 0; nt < 16; nt++) {
            int c0 = n0w + nt * 8 + qk * 2;
            float bb0 = fc2_b[c0], bb1 = fc2_b[c0 + 1];
            int ucol = (c0 >> 1);
            habu[rlo * HA_U32_STRIDE + ucol] =
                pack_bf16(fmaxf(d[nt][0] + bb0, 0.f), fmaxf(d[nt][1] + bb1, 0.f));
            habu[(rlo + 8) * HA_U32_STRIDE + ucol] =
                pack_bf16(fmaxf(d[nt][2] + bb0, 0.f), fmaxf(d[nt][3] + bb1, 0.f));
        }
    }
    // load fceT tile into H overlay (32 n x 256 k bf16, u32 stride 132)
    for (int idx = t; idx < 32 * 128; idx += 256) {
        int n = idx >> 7, j = idx & 127;
        Hu[n * FCE_U32_STRIDE + j] = ((const uint32_t*)g_fceT)[n * 128 + j];
    }
    __syncthreads();

    // ---- P4a: emb = h2 @ fce_w + fce_b via HMMA (M=64,N=32,K=256) ----------
    float e[2][4];
    {
#pragma unroll
        for (int nt = 0; nt < 2; nt++)
#pragma unroll
            for (int i = 0; i < 4; i++) e[nt][i] = 0.f;
#pragma unroll
        for (int ks = 0; ks < 16; ks++) {
            int aidx = (m0 + qrow) * HA_U32_STRIDE + ks * 8 + qk;
            uint32_t a0 = habu[aidx];
            uint32_t a1 = habu[aidx + 8 * HA_U32_STRIDE];
            uint32_t a2 = habu[aidx + 4];
            uint32_t a3 = habu[aidx + 8 * HA_U32_STRIDE + 4];
#pragma unroll
            for (int nt = 0; nt < 2; nt++) {
                int n = ng * 16 + nt * 8 + qrow;
                int bidx = n * FCE_U32_STRIDE + ks * 8 + qk;
                mma_bf16(e[nt][0], e[nt][1], e[nt][2], e[nt][3],
                         a0, a1, a2, a3, Hu[bidx], Hu[bidx + 4]);
            }
        }
    }
    // ---- act: sigmoid(h2 . fca_w + b) from bf16 h2 (own rows) --------------
    {
        float2 w2[4];
#pragma unroll
        for (int i = 0; i < 4; i++) w2[i] = ((const float2*)fca_w)[lane + 32 * i];
        for (int rr = 0; rr < 8; rr++) {
            int r = rbase + rr;
            float s = 0.f;
#pragma unroll
            for (int i = 0; i < 4; i++) {
                uint32_t hv = habu[r * HA_U32_STRIDE + lane + 32 * i];
                s = fmaf(bf16lo(hv), w2[i].x, s);
                s = fmaf(bf16hi(hv), w2[i].y, s);
            }
#pragma unroll
            for (int off = 16; off; off >>= 1) s += __shfl_xor_sync(0xffffffffu, s, off);
            if (lane == 0) ACT[r] = 1.f / (1.f + __expf(-(s + fca_b[0])));
        }
    }
    __syncthreads();   // h2 reads done; HA free for vsT overlay

    // write emb (regs) to EMB + load vsT into HA overlay
    {
#pragma unroll
        for (int nt = 0; nt < 2; nt++) {
            int c0 = ng * 16 + nt * 8 + qk * 2;
            float bb0 = fce_b[c0], bb1 = fce_b[c0 + 1];
            int ucol = ng * 8 + nt * 4 + qk;
            embu[(m0 + qrow) * EMB_U32_STRIDE + ucol] =
                pack_bf16(e[nt][0] + bb0, e[nt][1] + bb1);
            embu[(m0 + qrow + 8) * EMB_U32_STRIDE + ucol] =
                pack_bf16(e[nt][2] + bb0, e[nt][3] + bb1);
        }
        for (int idx = t; idx < 256 * 16; idx += 256) {
            int n = idx >> 4, j = idx & 15;
            VST[n * VST_U32_STRIDE + j] = ((const uint32_t*)g_vsTbf)[n * 16 + j];
        }
    }
    __syncthreads();

    // ---- P4b: relation = emb @ vsT^T via HMMA (M=64,N=256,K=32) ------------
    {
        const int vg = ng;
#pragma unroll
        for (int nt = 0; nt < 16; nt++)
#pragma unroll
            for (int i = 0; i < 4; i++) d[nt][i] = 0.f;
#pragma unroll
        for (int ks = 0; ks < 2; ks++) {
            int aidx = (m0 + qrow) * EMB_U32_STRIDE + ks * 8 + qk;
            uint32_t a0 = embu[aidx];
            uint32_t a1 = embu[aidx + 8 * EMB_U32_STRIDE];
            uint32_t a2 = embu[aidx + 4];
            uint32_t a3 = embu[aidx + 8 * EMB_U32_STRIDE + 4];
#pragma unroll
            for (int nt = 0; nt < 16; nt++) {
                int n = vg * 128 + nt * 8 + qrow;
                int bidx = n * VST_U32_STRIDE + ks * 8 + qk;
                mma_bf16(d[nt][0], d[nt][1], d[nt][2], d[nt][3],
                         a0, a1, a2, a3, VST[bidx], VST[bidx + 4]);
            }
        }
        int rlo = m0 + qrow;
#pragma unroll
        for (int nt = 0; nt < 16; nt++) {
            int c0 = vg * 128 + nt * 8 + qk * 2;
            *(float2*)&H[rlo * 256 + c0]       = make_float2(d[nt][0], d[nt][1]);
            *(float2*)&H[(rlo + 8) * 256 + c0] = make_float2(d[nt][2], d[nt][3]);
        }
    }
    __syncthreads();

    // ---- softmax * act over H rows (warp = 8 rows) -------------------------
    for (int rr = 0; rr < 8; rr++) {
        int r = rbase + rr;
        float4 ra = *(float4*)&H[r * 256 + lane * 8];
        float4 rb = *(float4*)&H[r * 256 + lane * 8 + 4];
        float m = fmaxf(fmaxf(fmaxf(ra.x, ra.y), fmaxf(ra.z, ra.w)),
                        fmaxf(fmaxf(rb.x, rb.y), fmaxf(rb.z, rb.w)));
#pragma unroll
        for (int off = 16; off; off >>= 1)
            m = fmaxf(m, __shfl_xor_sync(0xffffffffu, m, off));
        ra.x = __expf(ra.x - m); ra.y = __expf(ra.y - m);
        ra.z = __expf(ra.z - m); ra.w = __expf(ra.w - m);
        rb.x = __expf(rb.x - m); rb.y = __expf(rb.y - m);
        rb.z = __expf(rb.z - m); rb.w = __expf(rb.w - m);
        float s = ra.x + ra.y + ra.z + ra.w + rb.x + rb.y + rb.z + rb.w;
#pragma unroll
        for (int off = 16; off; off >>= 1) s += __shfl_xor_sync(0xffffffffu, s, off);
        float sc = ACT[r] / s;
        ra.x *= sc; ra.y *= sc; ra.z *= sc; ra.w *= sc;
        rb.x *= sc; rb.y *= sc; rb.z *= sc; rb.w *= sc;
        *(float4*)&H[r * 256 + lane * 8]     = ra;
        *(float4*)&H[r * 256 + lane * 8 + 4] = rb;
    }
    __syncthreads();

    // ---- P5: out[b,:,n0:n0+64] = view_cell[b] @ route^T --------------------
    // split-bf16 HMMA: acc = Ahi*Bhi + Ahi*Blo + Alo*Bhi (fp32 accum)
    // warps: wm = wid>>1 (4 x 32 c-rows), wn = wid&1 (2 x 32 n-cols)
    const int wm = wid >> 1, wn = wid & 1;
    float p5d[2][4][4];
#pragma unroll
    for (int mt = 0; mt < 2; mt++)
#pragma unroll
        for (int ntl = 0; ntl < 4; ntl++)
#pragma unroll
            for (int i = 0; i < 4; i++) p5d[mt][ntl][i] = 0.f;

    for (int vc = 0; vc < 8; vc++) {          // v-chunk of 32
        __syncthreads();
        {   // stage A hi/lo: 128 c-rows x 16 u32; thread -> (c = t>>1, half = t&1)
            int c = t >> 1, half = t & 1;
            int sidx = b * 16384 + c * 128 + vc * 16 + half * 8;
            const uint4* sh = (const uint4*)((const uint32_t*)g_vchi + sidx);
            const uint4* sl = (const uint4*)((const uint32_t*)g_vclo + sidx);
            uint4* dh = (uint4*)(AH + c * P5_STRIDE + half * 8);
            uint4* dl = (uint4*)(AL + c * P5_STRIDE + half * 8);
            dh[0] = sh[0]; dh[1] = sh[1];
            dl[0] = sl[0]; dl[1] = sl[1];
        }
        {   // convert route chunk fp32 -> hi/lo bf16 (64 n-rows x 32 v)
            int n = t >> 2, seg = t & 3;       // 8 fp32 per thread
            const float* src = H + n * 256 + vc * 32 + seg * 8;
            uint32_t* dh = BH + n * P5_STRIDE + seg * 4;
            uint32_t* dl = BL + n * P5_STRIDE + seg * 4;
#pragma unroll
            for (int j = 0; j < 4; j++) {
                float f0 = src[2 * j], f1 = src[2 * j + 1];
                uint32_t h = pack_bf16(f0, f1);
                dh[j] = h;
                dl[j] = pack_bf16(f0 - bf16lo(h), f1 - bf16hi(h));
            }
        }
        __syncthreads();
#pragma unroll
        for (int ks = 0; ks < 2; ks++) {
            uint32_t ah[2][4], al[2][4];
#pragma unroll
            for (int mt = 0; mt < 2; mt++) {
                int row = wm * 32 + mt * 16 + qrow;
                int aidx = row * P5_STRIDE + ks * 8 + qk;
                ah[mt][0] = AH[aidx];
                ah[mt][1] = AH[aidx + 8 * P5_STRIDE];
                ah[mt][2] = AH[aidx + 4];
                ah[mt][3] = AH[aidx + 8 * P5_STRIDE + 4];
                al[mt][0] = AL[aidx];
                al[mt][1] = AL[aidx + 8 * P5_STRIDE];
                al[mt][2] = AL[aidx + 4];
                al[mt][3] = AL[aidx + 8 * P5_STRIDE + 4];
            }
#pragma unroll
            for (int ntl = 0; ntl < 4; ntl++) {
                int n = wn * 32 + ntl * 8 + qrow;
                int bidx = n * P5_STRIDE + ks * 8 + qk;
                uint32_t bh0 = BH[bidx], bh1 = BH[bidx + 4];
                uint32_t bl0 = BL[bidx], bl1 = BL[bidx + 4];
#pragma unroll
                for (int mt = 0; mt < 2; mt++) {
                    mma_bf16(p5d[mt][ntl][0], p5d[mt][ntl][1], p5d[mt][ntl][2], p5d[mt][ntl][3],
                             ah[mt][0], ah[mt][1], ah[mt][2], ah[mt][3], bh0, bh1);
                    mma_bf16(p5d[mt][ntl][0], p5d[mt][ntl][1], p5d[mt][ntl][2], p5d[mt][ntl][3],
                             ah[mt][0], ah[mt][1], ah[mt][2], ah[mt][3], bl0, bl1);
                    mma_bf16(p5d[mt][ntl][0], p5d[mt][ntl][1], p5d[mt][ntl][2], p5d[mt][ntl][3],
                             al[mt][0], al[mt][1], al[mt][2], al[mt][3], bh0, bh1);
                }
            }
        }
    }

    // direct predicated stores: out[b][c][n], n contiguous
    float* outb = out + (size_t)b * kC * kN;
#pragma unroll
    for (int mt = 0; mt < 2; mt++) {
        int row = wm * 32 + mt * 16 + qrow;
        float* o0 = outb + (size_t)row * kN;
        float* o1 = o0 + 8 * kN;
#pragma unroll
        for (int ntl = 0; ntl < 4; ntl++) {
            int col = n0 + wn * 32 + ntl * 8 + qk * 2;
            if (col < kN) {
                *(float2*)&o0[col] = make_float2(p5d[mt][ntl][0], p5d[mt][ntl][1]);
                *(float2*)&o1[col] = make_float2(p5d[mt][ntl][2], p5d[mt][ntl][3]);
            }
        }
    }
}

// ---------------------------------------------------------------------------
extern "C" void kernel_launch(void* const* d_in, const int* in_sizes, int n_in,
                              void* d_out, int out_size) {
    const float* view_cell = (const float*)d_in[0];
    const float* v         = (const float*)d_in[1];
    const float* w2c_w1    = (const float*)d_in[2];
    const float* w2c_b1    = (const float*)d_in[3];
    const float* w2c_w2    = (const float*)d_in[4];
    const float* w2c_b2    = (const float*)d_in[5];
    const float* fc1_w     = (const float*)d_in[6];
    const float* fc1_b     = (const float*)d_in[7];
    const float* fc2_w     = (const float*)d_in[8];
    const float* fc2_b     = (const float*)d_in[9];
    const float* fca_w     = (const float*)d_in[10];
    const float* fca_b     = (const float*)d_in[11];
    const float* fce_w     = (const float*)d_in[12];
    const float* fce_b     = (const float*)d_in[13];
    const float* vse_w1    = (const float*)d_in[14];
    const float* vse_b1    = (const float*)d_in[15];
    const float* vse_w2    = (const float*)d_in[16];
    const float* vse_b2    = (const float*)d_in[17];
    float* out = (float*)d_out;

    cudaFuncSetAttribute(mega_kernel, cudaFuncAttributeMaxDynamicSharedMemorySize,
                         SM_BYTES);

    prep_kernel<<<2420, 512>>>(v, w2c_w1, w2c_b1, w2c_b2,
                               vse_w1, vse_b1, vse_w2, vse_b2,
                               fc2_w, fce_w, view_cell);

    dim3 wgrid(47, 8);
    wcode_kernel<<<wgrid, 128>>>(w2c_w2);

    dim3 grid((kN + TR - 1) / TR, kB);  // (32, 64)
    mega_kernel<<<grid, 256, SM_BYTES>>>(fc1_w, fc1_b, fc2_b,
                                         fca_w, fca_b, fce_b,
                                         out);
}

// round 16
// speedup vs baseline: 1.0865x; 1.0865x over previous
#include <cuda_runtime.h>
#include <cuda_bf16.h>
#include <cstdint>

// Problem constants
constexpr int kB   = 64;     // batch
constexpr int kC   = 128;    // CSIZE
constexpr int kV   = 256;    // VIEW
constexpr int kN   = 2000;   // N_WRD
constexpr int kE   = 32;     // EMB
constexpr int TR   = 128;    // n-rows per block

// shared memory layout (float indices)  — TR=128, 512 threads, 1 CTA/SM
constexpr int OFF_H   = 0;                      // 32768: P3 B-stage -> relation fp32 -> route-lo
constexpr int OFF_HA  = 32768;                  // 16512: h1/h2 bf16 -> route-hi (skewed)
constexpr int OFF_BUF = OFF_HA + 16512;         // 5184: fceT / vsT
constexpr int OFF_EMB = OFF_BUF + 5184;         // 2176: emb bf16, 128 x 17 u32
constexpr int OFF_WC  = OFF_EMB + 2176;         // 384
constexpr int OFF_ACT = OFF_WC + 384;           // 128
constexpr int SM_FLOATS = OFF_ACT + 128;        // 57152
constexpr int SM_BYTES  = SM_FLOATS * 4;        // 228608 B

constexpr int HA_U32_STRIDE  = 129;  // h1/h2: 258 bf16 per row
constexpr int BT_U32_STRIDE  = 68;   // P3 B chunk rows (128 bf16 = 64 u32 + 4 pad)
constexpr int FCE_U32_STRIDE = 132;  // fceT rows (256 bf16 + pad)
constexpr int VST_U32_STRIDE = 17;   // vsT rows (32 bf16 + pad)
constexpr int EMB_U32_STRIDE = 17;   // emb rows (32 bf16 + pad)

__device__ float g_h0[kB * 512];
__device__ float g_wcode[kB * 6000];
__device__ __align__(16) __nv_bfloat16 g_fc2bt[256 * 256];  // fc2 Bt[n][k]
__device__ __align__(16) __nv_bfloat16 g_fceT[32 * 256];    // fce Bt[n][k]
__device__ __align__(16) __nv_bfloat16 g_vsTbf[256 * 32];   // vs [v][e]
__device__ __align__(16) __nv_bfloat16 g_vchi[kB * kC * kV]; // view_cell hi
__device__ __align__(16) __nv_bfloat16 g_vclo[kB * kC * kV]; // view_cell lo

// ---------------- helpers ---------------------------------------------------
__device__ __forceinline__ uint32_t pack_bf16(float lo, float hi) {
    uint32_t r;
    asm("cvt.rn.bf16x2.f32 %0, %1, %2;" : "=r"(r) : "f"(hi), "f"(lo));
    return r;
}
__device__ __forceinline__ float bf16lo(uint32_t u) { return __uint_as_float(u << 16); }
__device__ __forceinline__ float bf16hi(uint32_t u) { return __uint_as_float(u & 0xffff0000u); }
__device__ __forceinline__ void mma_bf16(float& d0, float& d1, float& d2, float& d3,
                                         uint32_t a0, uint32_t a1, uint32_t a2, uint32_t a3,
                                         uint32_t b0, uint32_t b1) {
    asm volatile(
        "mma.sync.aligned.m16n8k16.row.col.f32.bf16.bf16.f32 "
        "{%0,%1,%2,%3}, {%4,%5,%6,%7}, {%8,%9}, {%0,%1,%2,%3};"
        : "+f"(d0), "+f"(d1), "+f"(d2), "+f"(d3)
        : "r"(a0), "r"(a1), "r"(a2), "r"(a3), "r"(b0), "r"(b1));
}

// ---------------------------------------------------------------------------
// Prep kernel (merged): all independent setup work in ONE launch.
// ---------------------------------------------------------------------------
__global__ __launch_bounds__(512)
void prep_kernel(const float* __restrict__ v,
                 const float* __restrict__ w2c_w1,
                 const float* __restrict__ w2c_b1,
                 const float* __restrict__ w2c_b2,
                 const float* __restrict__ vse_w1,
                 const float* __restrict__ vse_b1,
                 const float* __restrict__ vse_w2,
                 const float* __restrict__ vse_b2,
                 const float* __restrict__ fc2_w,
                 const float* __restrict__ fce_w,
                 const float* __restrict__ view_cell) {
    int blk = blockIdx.x;
    int t = threadIdx.x;  // 512
    if (blk < 64) {
        float acc = w2c_b1[t];
#pragma unroll
        for (int i = 0; i < 7; i++) acc += v[blk * 7 + i] * w2c_w1[i * 512 + t];
        g_h0[blk * 512 + t] = fmaxf(acc, 0.f);
    } else if (blk < 72) {
        int vb = (blk - 64) * 32;
        __shared__ float hid[32][128];
        for (int idx = t; idx < 32 * 128; idx += 512) {
            int vv = idx >> 7, h = idx & 127;
            int vg = vb + vv;
            int xi = vg >> 4, yi = vg & 15;
            float x = -1.f + (2.f / 15.f) * (float)xi;
            float y = -1.f + (2.f / 15.f) * (float)yi;
            float a = x * vse_w1[h] + y * vse_w1[128 + h] + vse_b1[h];
            hid[vv][h] = fmaxf(a, 0.f);
        }
        __syncthreads();
        for (int idx = t; idx < 32 * 32; idx += 512) {
            int e = idx >> 5, vv = idx & 31;
            float acc = vse_b2[e];
#pragma unroll 8
            for (int h = 0; h < 128; h++) acc += hid[vv][h] * vse_w2[h * kE + e];
            g_vsTbf[(vb + vv) * 32 + e] = __float2bfloat16(acc);
        }
    } else if (blk < 84) {
        for (int i = (blk - 72) * 512 + t; i < kB * 6000; i += 12 * 512) {
            int col = i % 6000;
            g_wcode[i] = w2c_b2[col];
        }
    } else if (blk < 340) {
        int p = (blk - 84) * 256 + (t & 255);   // 65536 elems over 256 blocks
        if (t < 256) {
            int k = p >> 8, n = p & 255;
            g_fc2bt[n * 256 + k] = __float2bfloat16(fc2_w[p]);
        }
    } else if (blk < 372) {
        int p = (blk - 340) * 256 + (t & 255);  // 8192 elems over 32 blocks
        if (t < 256) {
            int k = p >> 5, n = p & 31;
            g_fceT[n * 256 + k] = __float2bfloat16(fce_w[p]);
        }
    } else {
        int p = (blk - 372) * 512 + t;   // pair index, 1048576 pairs
        float2 f = ((const float2*)view_cell)[p];
        uint32_t h = pack_bf16(f.x, f.y);
        ((uint32_t*)g_vchi)[p] = h;
        ((uint32_t*)g_vclo)[p] = pack_bf16(f.x - bf16lo(h), f.y - bf16hi(h));
    }
}

// ---------------------------------------------------------------------------
// wcode: k-split GEMM with atomic accumulation (bias pre-written by prep).
// ---------------------------------------------------------------------------
__global__ __launch_bounds__(128)
void wcode_kernel(const float* __restrict__ w2c_w2) {
    __shared__ float h0s[64 * 65];  // [kk][b]
    int t = threadIdx.x;
    int col = blockIdx.x * 128 + t;
    int k0 = blockIdx.y * 64;
    bool ok = col < 6000;

    for (int idx = t; idx < 64 * 64; idx += 128) {
        int b = idx >> 6, kk = idx & 63;
        h0s[kk * 65 + b] = g_h0[b * 512 + k0 + kk];
    }
    __syncthreads();

    float acc[64];
#pragma unroll
    for (int b = 0; b < 64; b++) acc[b] = 0.f;
#pragma unroll 4
    for (int kk = 0; kk < 64; kk++) {
        float w = ok ? w2c_w2[(k0 + kk) * 6000 + col] : 0.f;
        const float* hrow = h0s + kk * 65;
#pragma unroll
        for (int b = 0; b < 64; b++) acc[b] = fmaf(hrow[b], w, acc[b]);
    }
    if (ok) {
#pragma unroll
        for (int b = 0; b < 64; b++) atomicAdd(&g_wcode[b * 6000 + col], acc[b]);
    }
}

// ---------------------------------------------------------------------------
// Mega kernel: one block = (batch b, 128 word rows). 512 threads, 1 CTA/SM.
// P3/P4a/P4b bf16 HMMA; P5 split-bf16 HMMA with direct-global A and resident
// skewed route hi/lo B (no staging, no P5 barriers).
// ---------------------------------------------------------------------------
__global__ __launch_bounds__(512, 1)
void mega_kernel(const float* __restrict__ fc1_w,  const float* __restrict__ fc1_b,
                 const float* __restrict__ fc2_b,
                 const float* __restrict__ fca_w,  const float* __restrict__ fca_b,
                 const float* __restrict__ fce_b,
                 float* __restrict__ out) {
    extern __shared__ float sm[];
    float*    H    = sm + OFF_H;                 // B-stage -> relation -> route-lo
    uint32_t* Hu   = (uint32_t*)H;
    uint32_t* habu = (uint32_t*)(sm + OFF_HA);   // h1/h2 bf16 -> route-hi (skewed)
    uint32_t* RHu  = habu;                       // route-hi overlay: row n at n*128, skewed
    uint32_t* bufu = (uint32_t*)(sm + OFF_BUF);  // fceT / vsT
    uint32_t* embu = (uint32_t*)(sm + OFF_EMB);  // emb bf16, u32 stride 17
    float*    WC   = sm + OFF_WC;
    float*    ACT  = sm + OFF_ACT;

    const int t    = threadIdx.x;
    const int lane = t & 31;
    const int wid  = t >> 5;          // 16 warps
    const int b    = blockIdx.y;
    const int n0   = blockIdx.x * TR;
    const int rbase = wid * 8;
    const int qrow = lane >> 2;       // 0..7
    const int qk   = lane & 3;        // 0..3

    // ---- P1: fetch wcode tile ----------------------------------------------
    if (t < 384) {
        int c = n0 * 3 + t;
        WC[t] = (c < 6000) ? g_wcode[b * 6000 + c] : 0.f;
    }
    __syncthreads();

    // ---- P2: h1 = relu(wcode @ fc1_w + b1) -> HA (bf16 pairs) --------------
    for (int p = t; p < 128 * 128; p += 512) {
        int row = p >> 7, j = p & 127;
        float wc0 = WC[row * 3 + 0], wc1 = WC[row * 3 + 1], wc2 = WC[row * 3 + 2];
        int c0 = 2 * j;
        float f0 = fmaxf(fc1_b[c0]     + wc0 * fc1_w[c0]     + wc1 * fc1_w[256 + c0]     + wc2 * fc1_w[512 + c0],     0.f);
        float f1 = fmaxf(fc1_b[c0 + 1] + wc0 * fc1_w[c0 + 1] + wc1 * fc1_w[256 + c0 + 1] + wc2 * fc1_w[512 + c0 + 1], 0.f);
        habu[row * HA_U32_STRIDE + j] = pack_bf16(f0, f1);
    }

    // ---- P3: h2 = relu(h1 @ fc2_w + b2) via bf16 HMMA (K in 2 chunks) ------
    const int rg = wid >> 1, ng = wid & 1;
    const int m0 = rg * 16;
    const int n0w = ng * 128;

    float d[16][4];
#pragma unroll
    for (int nt = 0; nt < 16; nt++)
#pragma unroll
        for (int i = 0; i < 4; i++) d[nt][i] = 0.f;

    for (int kc = 0; kc < 2; kc++) {           // k-chunks of 128
        __syncthreads();
        {   // copy B chunk: g_fc2bt[n][kc*128..+128] -> Hu[n][68 u32]
            int n = t >> 1, half = t & 1;
            const uint4* src = (const uint4*)g_fc2bt + n * 32 + kc * 16 + half * 8;
            uint4* dst = (uint4*)(Hu + n * BT_U32_STRIDE + half * 32);
#pragma unroll
            for (int j = 0; j < 8; j++) dst[j] = src[j];
        }
        __syncthreads();
#pragma unroll
        for (int ks = 0; ks < 8; ks++) {
            int aw = kc * 64 + ks * 8;     // A k-word base
            int aidx = (m0 + qrow) * HA_U32_STRIDE + aw + qk;
            uint32_t a0 = habu[aidx];
            uint32_t a1 = habu[aidx + 8 * HA_U32_STRIDE];
            uint32_t a2 = habu[aidx + 4];
            uint32_t a3 = habu[aidx + 8 * HA_U32_STRIDE + 4];
#pragma unroll
            for (int nt = 0; nt < 16; nt++) {
                int c = n0w + nt * 8 + qrow;
                int bidx = c * BT_U32_STRIDE + ks * 8 + qk;
                mma_bf16(d[nt][0], d[nt][1], d[nt][2], d[nt][3],
                         a0, a1, a2, a3, Hu[bidx], Hu[bidx + 4]);
            }
        }
    }
    __syncthreads();
    // writeback h2 = relu(d + fc2_b) as bf16 into HA (h1 dead)
    {
        int rlo = m0 + qrow;
#pragma unroll
        for (int nt = 0; nt < 16; nt++) {
            int c0 = n0w + nt * 8 + qk * 2;
            float bb0 = fc2_b[c0], bb1 = fc2_b[c0 + 1];
            int ucol = (c0 >> 1);
            habu[rlo * HA_U32_STRIDE + ucol] =
                pack_bf16(fmaxf(d[nt][0] + bb0, 0.f), fmaxf(d[nt][1] + bb1, 0.f));
            habu[(rlo + 8) * HA_U32_STRIDE + ucol] =
                pack_bf16(fmaxf(d[nt][2] + bb0, 0.f), fmaxf(d[nt][3] + bb1, 0.f));
        }
    }
    // load fceT tile into BUF (32 n x 256 k bf16, u32 stride 132)
    for (int idx = t; idx < 32 * 128; idx += 512) {
        int n = idx >> 7, j = idx & 127;
        bufu[n * FCE_U32_STRIDE + j] = ((const uint32_t*)g_fceT)[n * 128 + j];
    }
    __syncthreads();

    // ---- P4a: emb = h2 @ fce_w + fce_b via HMMA (M=128,N=32,K=256) ---------
    {
        float e[2][4];
#pragma unroll
        for (int nt = 0; nt < 2; nt++)
#pragma unroll
            for (int i = 0; i < 4; i++) e[nt][i] = 0.f;
#pragma unroll
        for (int ks = 0; ks < 16; ks++) {
            int aidx = (m0 + qrow) * HA_U32_STRIDE + ks * 8 + qk;
            uint32_t a0 = habu[aidx];
            uint32_t a1 = habu[aidx + 8 * HA_U32_STRIDE];
            uint32_t a2 = habu[aidx + 4];
            uint32_t a3 = habu[aidx + 8 * HA_U32_STRIDE + 4];
#pragma unroll
            for (int nt = 0; nt < 2; nt++) {
                int n = ng * 16 + nt * 8 + qrow;
                int bidx = n * FCE_U32_STRIDE + ks * 8 + qk;
                mma_bf16(e[nt][0], e[nt][1], e[nt][2], e[nt][3],
                         a0, a1, a2, a3, bufu[bidx], bufu[bidx + 4]);
            }
        }
#pragma unroll
        for (int nt = 0; nt < 2; nt++) {
            int c0 = ng * 16 + nt * 8 + qk * 2;
            float bb0 = fce_b[c0], bb1 = fce_b[c0 + 1];
            int ucol = ng * 8 + nt * 4 + qk;
            embu[(m0 + qrow) * EMB_U32_STRIDE + ucol] =
                pack_bf16(e[nt][0] + bb0, e[nt][1] + bb1);
            embu[(m0 + qrow + 8) * EMB_U32_STRIDE + ucol] =
                pack_bf16(e[nt][2] + bb0, e[nt][3] + bb1);
        }
    }
    // ---- act: sigmoid(h2 . fca_w + b) from bf16 h2 (own rows) --------------
    {
        float2 w2[4];
#pragma unroll
        for (int i = 0; i < 4; i++) w2[i] = ((const float2*)fca_w)[lane + 32 * i];
        for (int rr = 0; rr < 8; rr++) {
            int r = rbase + rr;
            float s = 0.f;
#pragma unroll
            for (int i = 0; i < 4; i++) {
                uint32_t hv = habu[r * HA_U32_STRIDE + lane + 32 * i];
                s = fmaf(bf16lo(hv), w2[i].x, s);
                s = fmaf(bf16hi(hv), w2[i].y, s);
            }
#pragma unroll
            for (int off = 16; off; off >>= 1) s += __shfl_xor_sync(0xffffffffu, s, off);
            if (lane == 0) ACT[r] = 1.f / (1.f + __expf(-(s + fca_b[0])));
        }
    }
    __syncthreads();

    // load vsT tile into BUF (256 v x 32 e bf16, u32 stride 17)
    for (int idx = t; idx < 256 * 16; idx += 512) {
        int n = idx >> 4, j = idx & 15;
        bufu[n * VST_U32_STRIDE + j] = ((const uint32_t*)g_vsTbf)[n * 16 + j];
    }
    __syncthreads();

    // ---- P4b: relation = emb @ vsT^T via HMMA (M=128,N=256,K=32) -----------
    {
        const int vg = ng;
#pragma unroll
        for (int nt = 0; nt < 16; nt++)
#pragma unroll
            for (int i = 0; i < 4; i++) d[nt][i] = 0.f;
#pragma unroll
        for (int ks = 0; ks < 2; ks++) {
            int aidx = (m0 + qrow) * EMB_U32_STRIDE + ks * 8 + qk;
            uint32_t a0 = embu[aidx];
            uint32_t a1 = embu[aidx + 8 * EMB_U32_STRIDE];
            uint32_t a2 = embu[aidx + 4];
            uint32_t a3 = embu[aidx + 8 * EMB_U32_STRIDE + 4];
#pragma unroll
            for (int nt = 0; nt < 16; nt++) {
                int n = vg * 128 + nt * 8 + qrow;
                int bidx = n * VST_U32_STRIDE + ks * 8 + qk;
                mma_bf16(d[nt][0], d[nt][1], d[nt][2], d[nt][3],
                         a0, a1, a2, a3, bufu[bidx], bufu[bidx + 4]);
            }
        }
        int rlo = m0 + qrow;
#pragma unroll
        for (int nt = 0; nt < 16; nt++) {
            int c0 = vg * 128 + nt * 8 + qk * 2;
            *(float2*)&H[rlo * 256 + c0]       = make_float2(d[nt][0], d[nt][1]);
            *(float2*)&H[(rlo + 8) * 256 + c0] = make_float2(d[nt][2], d[nt][3]);
        }
    }
    __syncthreads();

    // ---- softmax * act + fused route hi/lo split ---------------------------
    // hi -> RHu (HA overlay): row n at n*128, word w stored at (w + n*4) & 127
    // lo -> Hu in-place:      row n at n*256, word w stored at (w + n*4) & 127
    // (row-private: each warp reads/writes only its own 8 rows; reads precede
    //  writes within each row iteration)
    for (int rr = 0; rr < 8; rr++) {
        int r = rbase + rr;
        float4 ra = *(float4*)&H[r * 256 + lane * 8];
        float4 rb = *(float4*)&H[r * 256 + lane * 8 + 4];
        float m = fmaxf(fmaxf(fmaxf(ra.x, ra.y), fmaxf(ra.z, ra.w)),
                        fmaxf(fmaxf(rb.x, rb.y), fmaxf(rb.z, rb.w)));
#pragma unroll
        for (int off = 16; off; off >>= 1)
            m = fmaxf(m, __shfl_xor_sync(0xffffffffu, m, off));
        ra.x = __expf(ra.x - m); ra.y = __expf(ra.y - m);
        ra.z = __expf(ra.z - m); ra.w = __expf(ra.w - m);
        rb.x = __expf(rb.x - m); rb.y = __expf(rb.y - m);
        rb.z = __expf(rb.z - m); rb.w = __expf(rb.w - m);
        float s = ra.x + ra.y + ra.z + ra.w + rb.x + rb.y + rb.z + rb.w;
#pragma unroll
        for (int off = 16; off; off >>= 1) s += __shfl_xor_sync(0xffffffffu, s, off);
        float sc = ACT[r] / s;
        ra.x *= sc; ra.y *= sc; ra.z *= sc; ra.w *= sc;
        rb.x *= sc; rb.y *= sc; rb.z *= sc; rb.w *= sc;
        uint32_t h0 = pack_bf16(ra.x, ra.y);
        uint32_t h1 = pack_bf16(ra.z, ra.w);
        uint32_t h2 = pack_bf16(rb.x, rb.y);
        uint32_t h3 = pack_bf16(rb.z, rb.w);
        uint32_t l0 = pack_bf16(ra.x - bf16lo(h0), ra.y - bf16hi(h0));
        uint32_t l1 = pack_bf16(ra.z - bf16lo(h1), ra.w - bf16hi(h1));
        uint32_t l2 = pack_bf16(rb.x - bf16lo(h2), rb.y - bf16hi(h2));
        uint32_t l3 = pack_bf16(rb.z - bf16lo(h3), rb.w - bf16hi(h3));
        int wbase = (lane * 4 + r * 4) & 127;
        *(uint4*)&RHu[r * 128 + wbase] = make_uint4(h0, h1, h2, h3);
        *(uint4*)&Hu[r * 256 + wbase]  = make_uint4(l0, l1, l2, l3);
    }
    __syncthreads();

    // ---- P5: out[b,:,n0:n0+128] = view_cell[b] @ route^T -------------------
    // split-bf16 HMMA: acc = Ahi*Bhi + Ahi*Blo + Alo*Bhi.
    // A fragments direct from global (L1/L2-resident); B from RHu/Hu skewed.
    const int wm = wid >> 2, wn = wid & 3;
    const uint32_t* GH = (const uint32_t*)g_vchi + b * 16384;
    const uint32_t* GL = (const uint32_t*)g_vclo + b * 16384;

    float p5d[2][4][4];
#pragma unroll
    for (int mt = 0; mt < 2; mt++)
#pragma unroll
        for (int ntl = 0; ntl < 4; ntl++)
#pragma unroll
            for (int i = 0; i < 4; i++) p5d[mt][ntl][i] = 0.f;

#pragma unroll 4
    for (int ks = 0; ks < 16; ks++) {
        uint32_t ah[2][4], al[2][4];
#pragma unroll
        for (int mt = 0; mt < 2; mt++) {
            int row = wm * 32 + mt * 16 + qrow;
            int gidx = row * 128 + ks * 8 + qk;
            ah[mt][0] = GH[gidx];
            ah[mt][1] = GH[gidx + 8 * 128];
            ah[mt][2] = GH[gidx + 4];
            ah[mt][3] = GH[gidx + 8 * 128 + 4];
            al[mt][0] = GL[gidx];
            al[mt][1] = GL[gidx + 8 * 128];
            al[mt][2] = GL[gidx + 4];
            al[mt][3] = GL[gidx + 8 * 128 + 4];
        }
#pragma unroll
        for (int ntl = 0; ntl < 4; ntl++) {
            int n = wn * 32 + ntl * 8 + qrow;
            int w0 = (ks * 8 + qk + n * 4) & 127;
            int w1 = (ks * 8 + qk + 4 + n * 4) & 127;
            uint32_t bh0 = RHu[n * 128 + w0], bh1 = RHu[n * 128 + w1];
            uint32_t bl0 = Hu[n * 256 + w0],  bl1 = Hu[n * 256 + w1];
#pragma unroll
            for (int mt = 0; mt < 2; mt++) {
                mma_bf16(p5d[mt][ntl][0], p5d[mt][ntl][1], p5d[mt][ntl][2], p5d[mt][ntl][3],
                         ah[mt][0], ah[mt][1], ah[mt][2], ah[mt][3], bh0, bh1);
                mma_bf16(p5d[mt][ntl][0], p5d[mt][ntl][1], p5d[mt][ntl][2], p5d[mt][ntl][3],
                         ah[mt][0], ah[mt][1], ah[mt][2], ah[mt][3], bl0, bl1);
                mma_bf16(p5d[mt][ntl][0], p5d[mt][ntl][1], p5d[mt][ntl][2], p5d[mt][ntl][3],
                         al[mt][0], al[mt][1], al[mt][2], al[mt][3], bh0, bh1);
            }
        }
    }

    // direct predicated stores: out[b][c][n], n contiguous
    float* outb = out + (size_t)b * kC * kN;
#pragma unroll
    for (int mt = 0; mt < 2; mt++) {
        int row = wm * 32 + mt * 16 + qrow;
        float* o0 = outb + (size_t)row * kN;
        float* o1 = o0 + 8 * kN;
#pragma unroll
        for (int ntl = 0; ntl < 4; ntl++) {
            int col = n0 + wn * 32 + ntl * 8 + qk * 2;
            if (col < kN) {
                *(float2*)&o0[col] = make_float2(p5d[mt][ntl][0], p5d[mt][ntl][1]);
                *(float2*)&o1[col] = make_float2(p5d[mt][ntl][2], p5d[mt][ntl][3]);
            }
        }
    }
}

// ---------------------------------------------------------------------------
extern "C" void kernel_launch(void* const* d_in, const int* in_sizes, int n_in,
                              void* d_out, int out_size) {
    const float* view_cell = (const float*)d_in[0];
    const float* v         = (const float*)d_in[1];
    const float* w2c_w1    = (const float*)d_in[2];
    const float* w2c_b1    = (const float*)d_in[3];
    const float* w2c_w2    = (const float*)d_in[4];
    const float* w2c_b2    = (const float*)d_in[5];
    const float* fc1_w     = (const float*)d_in[6];
    const float* fc1_b     = (const float*)d_in[7];
    const float* fc2_w     = (const float*)d_in[8];
    const float* fc2_b     = (const float*)d_in[9];
    const float* fca_w     = (const float*)d_in[10];
    const float* fca_b     = (const float*)d_in[11];
    const float* fce_w     = (const float*)d_in[12];
    const float* fce_b     = (const float*)d_in[13];
    const float* vse_w1    = (const float*)d_in[14];
    const float* vse_b1    = (const float*)d_in[15];
    const float* vse_w2    = (const float*)d_in[16];
    const float* vse_b2    = (const float*)d_in[17];
    float* out = (float*)d_out;

    cudaFuncSetAttribute(mega_kernel, cudaFuncAttributeMaxDynamicSharedMemorySize,
                         SM_BYTES);

    prep_kernel<<<2420, 512>>>(v, w2c_w1, w2c_b1, w2c_b2,
                               vse_w1, vse_b1, vse_w2, vse_b2,
                               fc2_w, fce_w, view_cell);

    dim3 wgrid(47, 8);
    wcode_kernel<<<wgrid, 128>>>(w2c_w2);

    dim3 grid((kN + TR - 1) / TR, kB);  // (16, 64)
    mega_kernel<<<grid, 512, SM_BYTES>>>(fc1_w, fc1_b, fc2_b,
                                         fca_w, fca_b, fce_b,
                                         out);
}